// round 1
// baseline (speedup 1.0000x reference)
#include <cuda_runtime.h>
#include <math.h>

// Problem shape (fixed by the dataset)
#define B_BATCH 4
#define T_SEQ   2048
#define C_IN    1024
#define NQK     256     // 2*h : [Q1 | Q2]
#define HO      128
#define SCALE_F 0.08838834764831845f   // 128^-0.5
#define LAMBDA_INIT 0.8f

// Scratch (device globals: no allocation allowed in kernel_launch)
__device__ float g_Q[B_BATCH * T_SEQ * NQK];   // 8.4 MB
__device__ float g_K[B_BATCH * T_SEQ * NQK];   // 8.4 MB
__device__ float g_V[B_BATCH * T_SEQ * HO];    // 4.2 MB
__device__ float g_lambda;

// ---------------------------------------------------------------------------
// GEMM: C[M,N] = A[M,1024] @ W[1024,N], M=8192, N in {256,128}
// Block tile 128x64, BK=16, 256 threads, 8x4 per-thread microtile.
// ---------------------------------------------------------------------------
#define GBK 16
__global__ __launch_bounds__(256) void gemm_kernel(
    const float* __restrict__ A, const float* __restrict__ W,
    float* __restrict__ C, int N)
{
    __shared__ float As[GBK][132];   // transposed: As[k][row], pad to 132
    __shared__ float Ws[GBK][68];    // Ws[k][col], pad to 68

    const int tid = threadIdx.x;
    const int tx = tid & 15;         // col group: cols tx*4 .. tx*4+3
    const int ty = tid >> 4;         // row group: rows ty*8 .. ty*8+7
    const int row0 = blockIdx.y * 128;
    const int col0 = blockIdx.x * 64;

    float acc[8][4];
#pragma unroll
    for (int r = 0; r < 8; r++)
#pragma unroll
        for (int c = 0; c < 4; c++) acc[r][c] = 0.f;

    for (int kt = 0; kt < C_IN; kt += GBK) {
        // Load A tile 128x16 (transposed into As)
#pragma unroll
        for (int i = 0; i < 2; i++) {
            int idx = tid + i * 256;        // 0..511 float4s
            int ar = idx >> 2;              // 0..127
            int kq = idx & 3;               // 0..3
            float4 a = *(const float4*)&A[(size_t)(row0 + ar) * C_IN + kt + kq * 4];
            As[kq * 4 + 0][ar] = a.x;
            As[kq * 4 + 1][ar] = a.y;
            As[kq * 4 + 2][ar] = a.z;
            As[kq * 4 + 3][ar] = a.w;
        }
        // Load W tile 16x64
        {
            int k = tid >> 4;               // 0..15
            int nq = tid & 15;              // 0..15
            *(float4*)&Ws[k][nq * 4] =
                *(const float4*)&W[(size_t)(kt + k) * N + col0 + nq * 4];
        }
        __syncthreads();

#pragma unroll
        for (int kk = 0; kk < GBK; kk++) {
            float4 a0 = *(const float4*)&As[kk][ty * 8];
            float4 a1 = *(const float4*)&As[kk][ty * 8 + 4];
            float4 bb = *(const float4*)&Ws[kk][tx * 4];
            float av[8] = {a0.x, a0.y, a0.z, a0.w, a1.x, a1.y, a1.z, a1.w};
            float bv[4] = {bb.x, bb.y, bb.z, bb.w};
#pragma unroll
            for (int r = 0; r < 8; r++)
#pragma unroll
                for (int c = 0; c < 4; c++)
                    acc[r][c] += av[r] * bv[c];
        }
        __syncthreads();
    }

#pragma unroll
    for (int r = 0; r < 8; r++) {
        float4 o = make_float4(acc[r][0], acc[r][1], acc[r][2], acc[r][3]);
        *(float4*)&C[(size_t)(row0 + ty * 8 + r) * N + col0 + tx * 4] = o;
    }
}

// ---------------------------------------------------------------------------
// Lambda scalar: exp(dot(lq1,lk1)) - exp(dot(lq2,lk2)) + 0.8
// ---------------------------------------------------------------------------
__global__ void lambda_kernel(const float* __restrict__ lq1, const float* __restrict__ lk1,
                              const float* __restrict__ lq2, const float* __restrict__ lk2)
{
    __shared__ float r1[4], r2[4];
    int t = threadIdx.x;                     // 128 threads
    float d1 = lq1[t] * lk1[t];
    float d2 = lq2[t] * lk2[t];
#pragma unroll
    for (int o = 16; o; o >>= 1) {
        d1 += __shfl_xor_sync(0xffffffffu, d1, o);
        d2 += __shfl_xor_sync(0xffffffffu, d2, o);
    }
    if ((t & 31) == 0) { r1[t >> 5] = d1; r2[t >> 5] = d2; }
    __syncthreads();
    if (t == 0) {
        float a = r1[0] + r1[1] + r1[2] + r1[3];
        float b = r2[0] + r2[1] + r2[2] + r2[3];
        g_lambda = expf(a) - expf(b) + LAMBDA_INIT;
    }
}

// ---------------------------------------------------------------------------
// Fused dual-softmax causal (diag=+1) flash attention.
// BM=BN=32, 256 threads, 1 query row per thread (ty=tid>>3),
// 4 key columns per thread at col = tx + 8*c (conflict-free K reads),
// output dims per thread: d = tx*4 + 32*q (conflict-free V reads).
// Work balancing: block p handles q-tiles {p, 63-p} -> constant ~67 key tiles.
// ---------------------------------------------------------------------------
#define QS_STRIDE 260
#define VS_STRIDE 132
#define ATTN_SMEM ((2 * 32 * QS_STRIDE + 32 * VS_STRIDE) * (int)sizeof(float))

__global__ __launch_bounds__(256) void attn_kernel(float* __restrict__ out)
{
    extern __shared__ float smem[];
    float* Qs = smem;                        // [32][260]
    float* Ks = smem + 32 * QS_STRIDE;       // [32][260]
    float* Vs = smem + 2 * 32 * QS_STRIDE;   // [32][132]

    const int tid = threadIdx.x;
    const int tx = tid & 7;
    const int ty = tid >> 3;                 // query row within tile
    const int b = blockIdx.y;
    const int p = blockIdx.x;                // pair index 0..31
    const float lambda = g_lambda;

    const float* Qg = g_Q + (size_t)b * T_SEQ * NQK;
    const float* Kg = g_K + (size_t)b * T_SEQ * NQK;
    const float* Vg = g_V + (size_t)b * T_SEQ * HO;

    for (int half = 0; half < 2; half++) {
        const int qt = half ? (63 - p) : p;
        __syncthreads();
        // Load Q tile [32][256]
#pragma unroll
        for (int i = 0; i < 8; i++) {
            int idx = tid + i * 256;         // float4 index 0..2047
            int r = idx >> 6, k4 = idx & 63;
            *(float4*)&Qs[r * QS_STRIDE + k4 * 4] =
                *(const float4*)&Qg[(size_t)(qt * 32 + r) * NQK + k4 * 4];
        }

        float m1 = -1e30f, m2 = -1e30f, l1 = 0.f, l2 = 0.f;
        float4 acc1[4], acc2[4];
#pragma unroll
        for (int qd = 0; qd < 4; qd++) {
            acc1[qd] = make_float4(0.f, 0.f, 0.f, 0.f);
            acc2[qd] = make_float4(0.f, 0.f, 0.f, 0.f);
        }
        const int gi = qt * 32 + ty;
        const int nkt = min(qt + 2, 64);     // diag=+1 reaches one tile past qt

        for (int kt = 0; kt < nkt; kt++) {
            __syncthreads();
            // Load K tile [32][256], V tile [32][128]
#pragma unroll
            for (int i = 0; i < 8; i++) {
                int idx = tid + i * 256;
                int r = idx >> 6, k4 = idx & 63;
                *(float4*)&Ks[r * QS_STRIDE + k4 * 4] =
                    *(const float4*)&Kg[(size_t)(kt * 32 + r) * NQK + k4 * 4];
            }
#pragma unroll
            for (int i = 0; i < 4; i++) {
                int idx = tid + i * 256;
                int r = idx >> 5, d4 = idx & 31;
                *(float4*)&Vs[r * VS_STRIDE + d4 * 4] =
                    *(const float4*)&Vg[(size_t)(kt * 32 + r) * HO + d4 * 4];
            }
            __syncthreads();

            // ---- scores: two 128-dim dot products per (row, col) ----
            float s1[4] = {0.f, 0.f, 0.f, 0.f};
            float s2[4] = {0.f, 0.f, 0.f, 0.f};
            const float* qrow = &Qs[ty * QS_STRIDE];
#pragma unroll 4
            for (int kk = 0; kk < 128; kk += 4) {
                float4 q1 = *(const float4*)&qrow[kk];
                float4 q2 = *(const float4*)&qrow[128 + kk];
#pragma unroll
                for (int c = 0; c < 4; c++) {
                    const float* krow = &Ks[(tx + 8 * c) * QS_STRIDE];
                    float4 k1 = *(const float4*)&krow[kk];
                    float4 k2 = *(const float4*)&krow[128 + kk];
                    s1[c] += q1.x * k1.x + q1.y * k1.y + q1.z * k1.z + q1.w * k1.w;
                    s2[c] += q2.x * k2.x + q2.y * k2.y + q2.z * k2.z + q2.w * k2.w;
                }
            }

            // ---- mask + scale ----
#pragma unroll
            for (int c = 0; c < 4; c++) {
                int gj = kt * 32 + tx + 8 * c;
                bool msk = (gj > gi + 1);
                s1[c] = msk ? -1e30f : s1[c] * SCALE_F;
                s2[c] = msk ? -1e30f : s2[c] * SCALE_F;
            }

            // ---- online softmax (both streams), row spread over 8 lanes ----
            float mt1 = fmaxf(fmaxf(s1[0], s1[1]), fmaxf(s1[2], s1[3]));
            float mt2 = fmaxf(fmaxf(s2[0], s2[1]), fmaxf(s2[2], s2[3]));
#pragma unroll
            for (int o = 1; o < 8; o <<= 1) {
                mt1 = fmaxf(mt1, __shfl_xor_sync(0xffffffffu, mt1, o));
                mt2 = fmaxf(mt2, __shfl_xor_sync(0xffffffffu, mt2, o));
            }
            float mn1 = fmaxf(m1, mt1), mn2 = fmaxf(m2, mt2);
            float cr1 = __expf(m1 - mn1), cr2 = __expf(m2 - mn2);
            m1 = mn1; m2 = mn2;

            float pr1[4], pr2[4];
            float ps1 = 0.f, ps2 = 0.f;
#pragma unroll
            for (int c = 0; c < 4; c++) {
                pr1[c] = __expf(s1[c] - mn1); ps1 += pr1[c];
                pr2[c] = __expf(s2[c] - mn2); ps2 += pr2[c];
            }
#pragma unroll
            for (int o = 1; o < 8; o <<= 1) {
                ps1 += __shfl_xor_sync(0xffffffffu, ps1, o);
                ps2 += __shfl_xor_sync(0xffffffffu, ps2, o);
            }
            l1 = l1 * cr1 + ps1;
            l2 = l2 * cr2 + ps2;
#pragma unroll
            for (int qd = 0; qd < 4; qd++) {
                acc1[qd].x *= cr1; acc1[qd].y *= cr1; acc1[qd].z *= cr1; acc1[qd].w *= cr1;
                acc2[qd].x *= cr2; acc2[qd].y *= cr2; acc2[qd].z *= cr2; acc2[qd].w *= cr2;
            }

            // ---- PV accumulate: broadcast p via width-8 shuffles ----
#pragma unroll
            for (int j = 0; j < 32; j++) {
                float pj1 = __shfl_sync(0xffffffffu, pr1[j >> 3], j & 7, 8);
                float pj2 = __shfl_sync(0xffffffffu, pr2[j >> 3], j & 7, 8);
                const float* vrow = &Vs[j * VS_STRIDE];
#pragma unroll
                for (int qd = 0; qd < 4; qd++) {
                    float4 vv = *(const float4*)&vrow[tx * 4 + 32 * qd];
                    acc1[qd].x += pj1 * vv.x; acc1[qd].y += pj1 * vv.y;
                    acc1[qd].z += pj1 * vv.z; acc1[qd].w += pj1 * vv.w;
                    acc2[qd].x += pj2 * vv.x; acc2[qd].y += pj2 * vv.y;
                    acc2[qd].z += pj2 * vv.z; acc2[qd].w += pj2 * vv.w;
                }
            }
        }

        // ---- finalize: out = acc1/l1 - lambda * acc2/l2 ----
        float inv1 = 1.f / l1;
        float inv2 = lambda / l2;
        float* orow = out + (size_t)(b * T_SEQ + gi) * HO;
#pragma unroll
        for (int qd = 0; qd < 4; qd++) {
            float4 o;
            o.x = acc1[qd].x * inv1 - acc2[qd].x * inv2;
            o.y = acc1[qd].y * inv1 - acc2[qd].y * inv2;
            o.z = acc1[qd].z * inv1 - acc2[qd].z * inv2;
            o.w = acc1[qd].w * inv1 - acc2[qd].w * inv2;
            *(float4*)&orow[tx * 4 + 32 * qd] = o;
        }
    }
}

// ---------------------------------------------------------------------------
// kernel_launch
// Inputs: q, k, v, Wq, Wk, Wv, lambda_q1, lambda_k1, lambda_q2, lambda_k2
// Output: float32 [4, 2048, 128]
// ---------------------------------------------------------------------------
extern "C" void kernel_launch(void* const* d_in, const int* in_sizes, int n_in,
                              void* d_out, int out_size)
{
    const float* q   = (const float*)d_in[0];
    const float* k   = (const float*)d_in[1];
    const float* v   = (const float*)d_in[2];
    const float* Wq  = (const float*)d_in[3];
    const float* Wk  = (const float*)d_in[4];
    const float* Wv  = (const float*)d_in[5];
    const float* lq1 = (const float*)d_in[6];
    const float* lk1 = (const float*)d_in[7];
    const float* lq2 = (const float*)d_in[8];
    const float* lk2 = (const float*)d_in[9];
    float* out = (float*)d_out;

    float *gQ, *gK, *gV;
    cudaGetSymbolAddress((void**)&gQ, g_Q);
    cudaGetSymbolAddress((void**)&gK, g_K);
    cudaGetSymbolAddress((void**)&gV, g_V);

    // Projections: M = B*T = 8192 rows
    gemm_kernel<<<dim3(NQK / 64, 64), 256>>>(q, Wq, gQ, NQK);
    gemm_kernel<<<dim3(NQK / 64, 64), 256>>>(k, Wk, gK, NQK);
    gemm_kernel<<<dim3(HO  / 64, 64), 256>>>(v, Wv, gV, HO);

    lambda_kernel<<<1, 128>>>(lq1, lk1, lq2, lk2);

    cudaFuncSetAttribute(attn_kernel,
                         cudaFuncAttributeMaxDynamicSharedMemorySize, ATTN_SMEM);
    attn_kernel<<<dim3(32, B_BATCH), 256, ATTN_SMEM>>>(out);
}

// round 5
// speedup vs baseline: 1.2415x; 1.2415x over previous
#include <cuda_runtime.h>
#include <cuda_bf16.h>
#include <math.h>
#include <cstdint>

// Problem shape (fixed by the dataset)
#define B_BATCH 4
#define T_SEQ   2048
#define C_IN    1024
#define NQK     256     // 2*h : [Q1 | Q2]
#define HO      128
#define SCALE_F 0.08838834764831845f   // 128^-0.5
#define LAMBDA_INIT 0.8f

// Scratch (device globals: no allocation allowed in kernel_launch)
__device__ float g_Q[B_BATCH * T_SEQ * NQK];   // 8.4 MB
__device__ float g_K[B_BATCH * T_SEQ * NQK];   // 8.4 MB
__device__ float g_V[B_BATCH * T_SEQ * HO];    // 4.2 MB
__device__ float g_lambda;
// Pre-transposed, bf16-split, k-packed weights: [N][K/2] uint32 (bf16x2)
__device__ uint32_t g_WqTH[NQK * 512], g_WqTL[NQK * 512];
__device__ uint32_t g_WkTH[NQK * 512], g_WkTL[NQK * 512];
__device__ uint32_t g_WvTH[HO  * 512], g_WvTL[HO  * 512];

// ===========================================================================
// helpers
// ===========================================================================
__device__ __forceinline__ float hif(float x) {
    return __bfloat162float(__float2bfloat16_rn(x));
}
// pack two floats into bf16x2: low half = 'even' (first k), high = 'odd'
__device__ __forceinline__ uint32_t bf16x2(float even, float odd) {
    uint32_t r;
    asm("cvt.rn.bf16x2.f32 %0, %1, %2;" : "=r"(r) : "f"(odd), "f"(even));
    return r;
}
__device__ __forceinline__ void mma_bf16(float* c, const uint32_t* a,
                                         uint32_t b0, uint32_t b1) {
    asm volatile(
        "mma.sync.aligned.m16n8k16.row.col.f32.bf16.bf16.f32 "
        "{%0,%1,%2,%3}, {%4,%5,%6,%7}, {%8,%9}, {%0,%1,%2,%3};"
        : "+f"(c[0]), "+f"(c[1]), "+f"(c[2]), "+f"(c[3])
        : "r"(a[0]), "r"(a[1]), "r"(a[2]), "r"(a[3]), "r"(b0), "r"(b1));
}

// ===========================================================================
// W transpose + bf16 split + k-pack: TH/TL[n*512 + k2] covers W[2k2..2k2+1][n]
// ===========================================================================
__global__ void wsplit_kernel(const float* __restrict__ W, uint32_t* __restrict__ TH,
                              uint32_t* __restrict__ TL, int N)
{
    int idx = blockIdx.x * 256 + threadIdx.x;    // over N*512
    int n = idx >> 9, k2 = idx & 511;
    float w0 = W[(size_t)(2 * k2) * N + n];
    float w1 = W[(size_t)(2 * k2 + 1) * N + n];
    float h0 = hif(w0), h1 = hif(w1);
    TH[idx] = bf16x2(w0, w1);
    TL[idx] = bf16x2(w0 - h0, w1 - h1);
}

// ===========================================================================
// Tensor-core GEMM (3x bf16 split): C[8192,N] = A[8192,1024] @ W[1024,N]
// Block tile 128x64, 8 warps (warp tile 32x32), Kc=32, double-buffered smem.
// Smem layout per buffer (uint32 words): AH[128*20] AL[128*20] WH[64*20] WL[64*20]
// stride 20 -> conflict-free fragment LDS.
// ===========================================================================
#define KC 32
#define NCHUNK (C_IN / KC)
#define BUF_WORDS 7680               // 2560+2560+1280+1280
#define AL_OFF 2560
#define WH_OFF 5120
#define WL_OFF 6400
#define GEMM_SMEM (2 * BUF_WORDS * 4)

__global__ __launch_bounds__(256) void gemm_tc_kernel(
    const float* __restrict__ Aq, const float* __restrict__ Ak, const float* __restrict__ Av)
{
    extern __shared__ uint32_t smw[];

    const int tid = threadIdx.x;
    const int lane = tid & 31;
    const int wid = tid >> 5;
    const int g = lane >> 2;         // 0..7
    const int q = lane & 3;          // 0..3
    const int wm = wid & 3;          // warp m group (32 rows)
    const int wn = wid >> 2;         // warp n group (32 cols)
    const int r0 = wm * 32;
    const int n0 = wn * 32;
    const int row0 = blockIdx.x * 128;

    const int by = blockIdx.y;       // 0..9
    const float* A;
    const uint32_t* WTH;
    const uint32_t* WTL;
    float* Cp;
    int N, ntile;
    if (by < 4)      { A = Aq; WTH = g_WqTH; WTL = g_WqTL; Cp = g_Q; N = NQK; ntile = by; }
    else if (by < 8) { A = Ak; WTH = g_WkTH; WTL = g_WkTL; Cp = g_K; N = NQK; ntile = by - 4; }
    else             { A = Av; WTH = g_WvTH; WTL = g_WvTL; Cp = g_V; N = HO;  ntile = by - 8; }
    const int col0 = ntile * 64;

    float acc[2][4][4];
#pragma unroll
    for (int mt = 0; mt < 2; mt++)
#pragma unroll
        for (int nt = 0; nt < 4; nt++)
#pragma unroll
            for (int i = 0; i < 4; i++) acc[mt][nt][i] = 0.f;

    // Per-chunk loader indices
    const int a_r[4] = { (tid + 0) >> 3, (tid + 256) >> 3, (tid + 512) >> 3, (tid + 768) >> 3 };
    const int a_c4 = tid & 7;
    const int w_n = tid >> 2;        // 0..63 (tile-local col)
    const int w_q = tid & 3;         // 0..3
    const size_t w_gn = (size_t)(col0 + w_n) * 512;   // global col base into WTH/WTL

    // ---- load chunk 0 ----
    {
        const int kt = 0;
        float4 ar[4];
#pragma unroll
        for (int i = 0; i < 4; i++)
            ar[i] = *(const float4*)&A[(size_t)(row0 + a_r[i]) * C_IN + kt + a_c4 * 4];
        uint4 wh = *(const uint4*)&WTH[w_gn + 0 + w_q * 4];
        uint4 wl = *(const uint4*)&WTL[w_gn + 0 + w_q * 4];
        uint32_t* AH = smw;
#pragma unroll
        for (int i = 0; i < 4; i++) {
            int base = a_r[i] * 20 + a_c4 * 2;
            float hx = hif(ar[i].x), hy = hif(ar[i].y), hz = hif(ar[i].z), hw = hif(ar[i].w);
            AH[base]              = bf16x2(ar[i].x, ar[i].y);
            AH[base + 1]          = bf16x2(ar[i].z, ar[i].w);
            AH[AL_OFF + base]     = bf16x2(ar[i].x - hx, ar[i].y - hy);
            AH[AL_OFF + base + 1] = bf16x2(ar[i].z - hz, ar[i].w - hw);
        }
        *(uint4*)&AH[WH_OFF + w_n * 20 + w_q * 4] = wh;
        *(uint4*)&AH[WL_OFF + w_n * 20 + w_q * 4] = wl;
    }
    __syncthreads();

    for (int c = 0; c < NCHUNK; c++) {
        const int buf = c & 1;
        const uint32_t* AHp = smw + buf * BUF_WORDS;

        // ---- issue next chunk's global loads ----
        float4 ar[4];
        uint4 wh, wl;
        const bool more = (c + 1 < NCHUNK);
        if (more) {
            const int kt = (c + 1) * KC;
#pragma unroll
            for (int i = 0; i < 4; i++)
                ar[i] = *(const float4*)&A[(size_t)(row0 + a_r[i]) * C_IN + kt + a_c4 * 4];
            wh = *(const uint4*)&WTH[w_gn + (c + 1) * 16 + w_q * 4];
            wl = *(const uint4*)&WTL[w_gn + (c + 1) * 16 + w_q * 4];
        }

        // ---- compute on current buffer ----
#pragma unroll
        for (int ks = 0; ks < 2; ks++) {
            uint32_t ah[2][4], al[2][4];
#pragma unroll
            for (int mt = 0; mt < 2; mt++) {
                int rb = (r0 + mt * 16 + g) * 20 + ks * 8 + q;
                ah[mt][0] = AHp[rb];
                ah[mt][1] = AHp[rb + 160];        // +8 rows
                ah[mt][2] = AHp[rb + 4];
                ah[mt][3] = AHp[rb + 164];
                al[mt][0] = AHp[AL_OFF + rb];
                al[mt][1] = AHp[AL_OFF + rb + 160];
                al[mt][2] = AHp[AL_OFF + rb + 4];
                al[mt][3] = AHp[AL_OFF + rb + 164];
            }
#pragma unroll
            for (int nt = 0; nt < 4; nt++) {
                int nb = (n0 + nt * 8 + g) * 20 + ks * 8 + q;
                uint32_t bh0 = AHp[WH_OFF + nb], bh1 = AHp[WH_OFF + nb + 4];
                uint32_t bl0 = AHp[WL_OFF + nb], bl1 = AHp[WL_OFF + nb + 4];
#pragma unroll
                for (int mt = 0; mt < 2; mt++) {
                    mma_bf16(acc[mt][nt], ah[mt], bh0, bh1);
                    mma_bf16(acc[mt][nt], ah[mt], bl0, bl1);
                    mma_bf16(acc[mt][nt], al[mt], bh0, bh1);
                }
            }
        }

        // ---- store next chunk into other buffer ----
        if (more) {
            uint32_t* AH = smw + (buf ^ 1) * BUF_WORDS;
#pragma unroll
            for (int i = 0; i < 4; i++) {
                int base = a_r[i] * 20 + a_c4 * 2;
                float hx = hif(ar[i].x), hy = hif(ar[i].y), hz = hif(ar[i].z), hw = hif(ar[i].w);
                AH[base]              = bf16x2(ar[i].x, ar[i].y);
                AH[base + 1]          = bf16x2(ar[i].z, ar[i].w);
                AH[AL_OFF + base]     = bf16x2(ar[i].x - hx, ar[i].y - hy);
                AH[AL_OFF + base + 1] = bf16x2(ar[i].z - hz, ar[i].w - hw);
            }
            *(uint4*)&AH[WH_OFF + w_n * 20 + w_q * 4] = wh;
            *(uint4*)&AH[WL_OFF + w_n * 20 + w_q * 4] = wl;
        }
        __syncthreads();
    }

    // ---- epilogue: fp32 stores ----
#pragma unroll
    for (int mt = 0; mt < 2; mt++) {
        int row = row0 + r0 + mt * 16 + g;
#pragma unroll
        for (int nt = 0; nt < 4; nt++) {
            int col = col0 + n0 + nt * 8 + 2 * q;
            float2 s0 = make_float2(acc[mt][nt][0], acc[mt][nt][1]);
            float2 s1 = make_float2(acc[mt][nt][2], acc[mt][nt][3]);
            *(float2*)&Cp[(size_t)row * N + col] = s0;
            *(float2*)&Cp[(size_t)(row + 8) * N + col] = s1;
        }
    }
}

// ---------------------------------------------------------------------------
// Lambda scalar: exp(dot(lq1,lk1)) - exp(dot(lq2,lk2)) + 0.8
// ---------------------------------------------------------------------------
__global__ void lambda_kernel(const float* __restrict__ lq1, const float* __restrict__ lk1,
                              const float* __restrict__ lq2, const float* __restrict__ lk2)
{
    __shared__ float r1[4], r2[4];
    int t = threadIdx.x;                     // 128 threads
    float d1 = lq1[t] * lk1[t];
    float d2 = lq2[t] * lk2[t];
#pragma unroll
    for (int o = 16; o; o >>= 1) {
        d1 += __shfl_xor_sync(0xffffffffu, d1, o);
        d2 += __shfl_xor_sync(0xffffffffu, d2, o);
    }
    if ((t & 31) == 0) { r1[t >> 5] = d1; r2[t >> 5] = d2; }
    __syncthreads();
    if (t == 0) {
        float a = r1[0] + r1[1] + r1[2] + r1[3];
        float b = r2[0] + r2[1] + r2[2] + r2[3];
        g_lambda = expf(a) - expf(b) + LAMBDA_INIT;
    }
}

// ---------------------------------------------------------------------------
// Fused dual-softmax causal (diag=+1) flash attention (unchanged from R1).
// ---------------------------------------------------------------------------
#define QS_STRIDE 260
#define VS_STRIDE 132
#define ATTN_SMEM ((2 * 32 * QS_STRIDE + 32 * VS_STRIDE) * (int)sizeof(float))

__global__ __launch_bounds__(256) void attn_kernel(float* __restrict__ out)
{
    extern __shared__ float smem[];
    float* Qs = smem;                        // [32][260]
    float* Ks = smem + 32 * QS_STRIDE;       // [32][260]
    float* Vs = smem + 2 * 32 * QS_STRIDE;   // [32][132]

    const int tid = threadIdx.x;
    const int tx = tid & 7;
    const int ty = tid >> 3;                 // query row within tile
    const int b = blockIdx.y;
    const int p = blockIdx.x;                // pair index 0..31
    const float lambda = g_lambda;

    const float* Qg = g_Q + (size_t)b * T_SEQ * NQK;
    const float* Kg = g_K + (size_t)b * T_SEQ * NQK;
    const float* Vg = g_V + (size_t)b * T_SEQ * HO;

    for (int half = 0; half < 2; half++) {
        const int qt = half ? (63 - p) : p;
        __syncthreads();
#pragma unroll
        for (int i = 0; i < 8; i++) {
            int idx = tid + i * 256;
            int r = idx >> 6, k4 = idx & 63;
            *(float4*)&Qs[r * QS_STRIDE + k4 * 4] =
                *(const float4*)&Qg[(size_t)(qt * 32 + r) * NQK + k4 * 4];
        }

        float m1 = -1e30f, m2 = -1e30f, l1 = 0.f, l2 = 0.f;
        float4 acc1[4], acc2[4];
#pragma unroll
        for (int qd = 0; qd < 4; qd++) {
            acc1[qd] = make_float4(0.f, 0.f, 0.f, 0.f);
            acc2[qd] = make_float4(0.f, 0.f, 0.f, 0.f);
        }
        const int gi = qt * 32 + ty;
        const int nkt = min(qt + 2, 64);

        for (int kt = 0; kt < nkt; kt++) {
            __syncthreads();
#pragma unroll
            for (int i = 0; i < 8; i++) {
                int idx = tid + i * 256;
                int r = idx >> 6, k4 = idx & 63;
                *(float4*)&Ks[r * QS_STRIDE + k4 * 4] =
                    *(const float4*)&Kg[(size_t)(kt * 32 + r) * NQK + k4 * 4];
            }
#pragma unroll
            for (int i = 0; i < 4; i++) {
                int idx = tid + i * 256;
                int r = idx >> 5, d4 = idx & 31;
                *(float4*)&Vs[r * VS_STRIDE + d4 * 4] =
                    *(const float4*)&Vg[(size_t)(kt * 32 + r) * HO + d4 * 4];
            }
            __syncthreads();

            float s1[4] = {0.f, 0.f, 0.f, 0.f};
            float s2[4] = {0.f, 0.f, 0.f, 0.f};
            const float* qrow = &Qs[ty * QS_STRIDE];
#pragma unroll 4
            for (int kk = 0; kk < 128; kk += 4) {
                float4 q1 = *(const float4*)&qrow[kk];
                float4 q2 = *(const float4*)&qrow[128 + kk];
#pragma unroll
                for (int c = 0; c < 4; c++) {
                    const float* krow = &Ks[(tx + 8 * c) * QS_STRIDE];
                    float4 k1 = *(const float4*)&krow[kk];
                    float4 k2 = *(const float4*)&krow[128 + kk];
                    s1[c] += q1.x * k1.x + q1.y * k1.y + q1.z * k1.z + q1.w * k1.w;
                    s2[c] += q2.x * k2.x + q2.y * k2.y + q2.z * k2.z + q2.w * k2.w;
                }
            }

#pragma unroll
            for (int c = 0; c < 4; c++) {
                int gj = kt * 32 + tx + 8 * c;
                bool msk = (gj > gi + 1);
                s1[c] = msk ? -1e30f : s1[c] * SCALE_F;
                s2[c] = msk ? -1e30f : s2[c] * SCALE_F;
            }

            float mt1 = fmaxf(fmaxf(s1[0], s1[1]), fmaxf(s1[2], s1[3]));
            float mt2 = fmaxf(fmaxf(s2[0], s2[1]), fmaxf(s2[2], s2[3]));
#pragma unroll
            for (int o = 1; o < 8; o <<= 1) {
                mt1 = fmaxf(mt1, __shfl_xor_sync(0xffffffffu, mt1, o));
                mt2 = fmaxf(mt2, __shfl_xor_sync(0xffffffffu, mt2, o));
            }
            float mn1 = fmaxf(m1, mt1), mn2 = fmaxf(m2, mt2);
            float cr1 = __expf(m1 - mn1), cr2 = __expf(m2 - mn2);
            m1 = mn1; m2 = mn2;

            float pr1[4], pr2[4];
            float ps1 = 0.f, ps2 = 0.f;
#pragma unroll
            for (int c = 0; c < 4; c++) {
                pr1[c] = __expf(s1[c] - mn1); ps1 += pr1[c];
                pr2[c] = __expf(s2[c] - mn2); ps2 += pr2[c];
            }
#pragma unroll
            for (int o = 1; o < 8; o <<= 1) {
                ps1 += __shfl_xor_sync(0xffffffffu, ps1, o);
                ps2 += __shfl_xor_sync(0xffffffffu, ps2, o);
            }
            l1 = l1 * cr1 + ps1;
            l2 = l2 * cr2 + ps2;
#pragma unroll
            for (int qd = 0; qd < 4; qd++) {
                acc1[qd].x *= cr1; acc1[qd].y *= cr1; acc1[qd].z *= cr1; acc1[qd].w *= cr1;
                acc2[qd].x *= cr2; acc2[qd].y *= cr2; acc2[qd].z *= cr2; acc2[qd].w *= cr2;
            }

#pragma unroll
            for (int j = 0; j < 32; j++) {
                float pj1 = __shfl_sync(0xffffffffu, pr1[j >> 3], j & 7, 8);
                float pj2 = __shfl_sync(0xffffffffu, pr2[j >> 3], j & 7, 8);
                const float* vrow = &Vs[j * VS_STRIDE];
#pragma unroll
                for (int qd = 0; qd < 4; qd++) {
                    float4 vv = *(const float4*)&vrow[tx * 4 + 32 * qd];
                    acc1[qd].x += pj1 * vv.x; acc1[qd].y += pj1 * vv.y;
                    acc1[qd].z += pj1 * vv.z; acc1[qd].w += pj1 * vv.w;
                    acc2[qd].x += pj2 * vv.x; acc2[qd].y += pj2 * vv.y;
                    acc2[qd].z += pj2 * vv.z; acc2[qd].w += pj2 * vv.w;
                }
            }
        }

        float inv1 = 1.f / l1;
        float inv2 = lambda / l2;
        float* orow = out + (size_t)(b * T_SEQ + gi) * HO;
#pragma unroll
        for (int qd = 0; qd < 4; qd++) {
            float4 o;
            o.x = acc1[qd].x * inv1 - acc2[qd].x * inv2;
            o.y = acc1[qd].y * inv1 - acc2[qd].y * inv2;
            o.z = acc1[qd].z * inv1 - acc2[qd].z * inv2;
            o.w = acc1[qd].w * inv1 - acc2[qd].w * inv2;
            *(float4*)&orow[tx * 4 + 32 * qd] = o;
        }
    }
}

// ---------------------------------------------------------------------------
// kernel_launch
// Inputs: q, k, v, Wq, Wk, Wv, lambda_q1, lambda_k1, lambda_q2, lambda_k2
// Output: float32 [4, 2048, 128]
// ---------------------------------------------------------------------------
extern "C" void kernel_launch(void* const* d_in, const int* in_sizes, int n_in,
                              void* d_out, int out_size)
{
    const float* q   = (const float*)d_in[0];
    const float* k   = (const float*)d_in[1];
    const float* v   = (const float*)d_in[2];
    const float* Wq  = (const float*)d_in[3];
    const float* Wk  = (const float*)d_in[4];
    const float* Wv  = (const float*)d_in[5];
    const float* lq1 = (const float*)d_in[6];
    const float* lk1 = (const float*)d_in[7];
    const float* lq2 = (const float*)d_in[8];
    const float* lk2 = (const float*)d_in[9];
    float* out = (float*)d_out;

    uint32_t *wqth, *wqtl, *wkth, *wktl, *wvth, *wvtl;
    cudaGetSymbolAddress((void**)&wqth, g_WqTH);
    cudaGetSymbolAddress((void**)&wqtl, g_WqTL);
    cudaGetSymbolAddress((void**)&wkth, g_WkTH);
    cudaGetSymbolAddress((void**)&wktl, g_WkTL);
    cudaGetSymbolAddress((void**)&wvth, g_WvTH);
    cudaGetSymbolAddress((void**)&wvtl, g_WvTL);

    // Transpose + bf16-split + pack weights
    wsplit_kernel<<<(NQK * 512) / 256, 256>>>(Wq, wqth, wqtl, NQK);
    wsplit_kernel<<<(NQK * 512) / 256, 256>>>(Wk, wkth, wktl, NQK);
    wsplit_kernel<<<(HO  * 512) / 256, 256>>>(Wv, wvth, wvtl, HO);

    // Projections on tensor cores (3x bf16 split mma.sync)
    cudaFuncSetAttribute(gemm_tc_kernel,
                         cudaFuncAttributeMaxDynamicSharedMemorySize, GEMM_SMEM);
    gemm_tc_kernel<<<dim3(64, 10), 256, GEMM_SMEM>>>(q, k, v);

    lambda_kernel<<<1, 128>>>(lq1, lk1, lq2, lk2);

    cudaFuncSetAttribute(attn_kernel,
                         cudaFuncAttributeMaxDynamicSharedMemorySize, ATTN_SMEM);
    attn_kernel<<<dim3(32, B_BATCH), 256, ATTN_SMEM>>>(out);
}

// round 6
// speedup vs baseline: 2.7477x; 2.2133x over previous
#include <cuda_runtime.h>
#include <cuda_bf16.h>
#include <math.h>
#include <cstdint>

// Problem shape (fixed by the dataset)
#define B_BATCH 4
#define T_SEQ   2048
#define C_IN    1024
#define NQK     256     // 2*h : [Q1 | Q2]
#define HO      128
#define SCALE_F 0.08838834764831845f   // 128^-0.5
#define LAMBDA_INIT 0.8f

// Scratch (device globals)
__device__ float g_lambda;
// Projected Q/K: bf16-split, k-packed: [8192 rows][128 words] (bf16x2 over dim pairs)
__device__ uint32_t g_QH[8192 * 128], g_QL[8192 * 128];
__device__ uint32_t g_KH[8192 * 128], g_KL[8192 * 128];
// Projected V, TRANSPOSED + key-packed: [128 dims][4096 words] (bf16x2 over token pairs)
__device__ uint32_t g_VH[128 * 4096], g_VL[128 * 4096];
// Per-stream attention outputs (normalized)
__device__ float g_O1[8192 * 128], g_O2[8192 * 128];
// Pre-transposed, bf16-split, k-packed weights: [N][K/2] uint32 (bf16x2)
__device__ uint32_t g_WqTH[NQK * 512], g_WqTL[NQK * 512];
__device__ uint32_t g_WkTH[NQK * 512], g_WkTL[NQK * 512];
__device__ uint32_t g_WvTH[HO  * 512], g_WvTL[HO  * 512];

// ===========================================================================
// helpers
// ===========================================================================
__device__ __forceinline__ float hif(float x) {
    return __bfloat162float(__float2bfloat16_rn(x));
}
// pack two floats into bf16x2: low half = 'even' (first k), high = 'odd'
__device__ __forceinline__ uint32_t bf16x2(float even, float odd) {
    uint32_t r;
    asm("cvt.rn.bf16x2.f32 %0, %1, %2;" : "=r"(r) : "f"(odd), "f"(even));
    return r;
}
__device__ __forceinline__ void mma_bf16(float* c, const uint32_t* a,
                                         uint32_t b0, uint32_t b1) {
    asm volatile(
        "mma.sync.aligned.m16n8k16.row.col.f32.bf16.bf16.f32 "
        "{%0,%1,%2,%3}, {%4,%5,%6,%7}, {%8,%9}, {%0,%1,%2,%3};"
        : "+f"(c[0]), "+f"(c[1]), "+f"(c[2]), "+f"(c[3])
        : "r"(a[0]), "r"(a[1]), "r"(a[2]), "r"(a[3]), "r"(b0), "r"(b1));
}

// ===========================================================================
// W transpose + bf16 split + k-pack
// ===========================================================================
__global__ void wsplit_kernel(const float* __restrict__ W, uint32_t* __restrict__ TH,
                              uint32_t* __restrict__ TL, int N)
{
    int idx = blockIdx.x * 256 + threadIdx.x;    // over N*512
    int n = idx >> 9, k2 = idx & 511;
    float w0 = W[(size_t)(2 * k2) * N + n];
    float w1 = W[(size_t)(2 * k2 + 1) * N + n];
    float h0 = hif(w0), h1 = hif(w1);
    TH[idx] = bf16x2(w0, w1);
    TL[idx] = bf16x2(w0 - h0, w1 - h1);
}

// ===========================================================================
// Tensor-core projection GEMM (3x bf16 split).
// by<4: Q (writes g_QH/g_QL), by<8: K, by 8..9: V (transposed write to g_VH/VL).
// ===========================================================================
#define KC 32
#define NCHUNK (C_IN / KC)
#define BUF_WORDS 7680
#define AL_OFF 2560
#define WH_OFF 5120
#define WL_OFF 6400
#define GEMM_SMEM (2 * BUF_WORDS * 4)

__global__ __launch_bounds__(256) void gemm_tc_kernel(
    const float* __restrict__ Aq, const float* __restrict__ Ak, const float* __restrict__ Av)
{
    extern __shared__ uint32_t smw[];

    const int tid = threadIdx.x;
    const int lane = tid & 31;
    const int wid = tid >> 5;
    const int g = lane >> 2;
    const int q = lane & 3;
    const int wm = wid & 3;
    const int wn = wid >> 2;
    const int r0 = wm * 32;
    const int n0 = wn * 32;
    const int row0 = blockIdx.x * 128;

    const int by = blockIdx.y;       // 0..9
    const float* A;
    const uint32_t* WTH;
    const uint32_t* WTL;
    int N, ntile;
    if (by < 4)      { A = Aq; WTH = g_WqTH; WTL = g_WqTL; N = NQK; ntile = by; }
    else if (by < 8) { A = Ak; WTH = g_WkTH; WTL = g_WkTL; N = NQK; ntile = by - 4; }
    else             { A = Av; WTH = g_WvTH; WTL = g_WvTL; N = HO;  ntile = by - 8; }
    const int col0 = ntile * 64;

    float acc[2][4][4];
#pragma unroll
    for (int mt = 0; mt < 2; mt++)
#pragma unroll
        for (int nt = 0; nt < 4; nt++)
#pragma unroll
            for (int i = 0; i < 4; i++) acc[mt][nt][i] = 0.f;

    const int a_r[4] = { (tid + 0) >> 3, (tid + 256) >> 3, (tid + 512) >> 3, (tid + 768) >> 3 };
    const int a_c4 = tid & 7;
    const int w_n = tid >> 2;
    const int w_q = tid & 3;
    const size_t w_gn = (size_t)(col0 + w_n) * 512;

    // ---- load chunk 0 ----
    {
        float4 ar[4];
#pragma unroll
        for (int i = 0; i < 4; i++)
            ar[i] = *(const float4*)&A[(size_t)(row0 + a_r[i]) * C_IN + a_c4 * 4];
        uint4 wh = *(const uint4*)&WTH[w_gn + w_q * 4];
        uint4 wl = *(const uint4*)&WTL[w_gn + w_q * 4];
        uint32_t* AH = smw;
#pragma unroll
        for (int i = 0; i < 4; i++) {
            int base = a_r[i] * 20 + a_c4 * 2;
            float hx = hif(ar[i].x), hy = hif(ar[i].y), hz = hif(ar[i].z), hw = hif(ar[i].w);
            AH[base]              = bf16x2(ar[i].x, ar[i].y);
            AH[base + 1]          = bf16x2(ar[i].z, ar[i].w);
            AH[AL_OFF + base]     = bf16x2(ar[i].x - hx, ar[i].y - hy);
            AH[AL_OFF + base + 1] = bf16x2(ar[i].z - hz, ar[i].w - hw);
        }
        *(uint4*)&AH[WH_OFF + w_n * 20 + w_q * 4] = wh;
        *(uint4*)&AH[WL_OFF + w_n * 20 + w_q * 4] = wl;
    }
    __syncthreads();

    for (int c = 0; c < NCHUNK; c++) {
        const int buf = c & 1;
        const uint32_t* AHp = smw + buf * BUF_WORDS;

        float4 ar[4];
        uint4 wh, wl;
        const bool more = (c + 1 < NCHUNK);
        if (more) {
            const int kt = (c + 1) * KC;
#pragma unroll
            for (int i = 0; i < 4; i++)
                ar[i] = *(const float4*)&A[(size_t)(row0 + a_r[i]) * C_IN + kt + a_c4 * 4];
            wh = *(const uint4*)&WTH[w_gn + (c + 1) * 16 + w_q * 4];
            wl = *(const uint4*)&WTL[w_gn + (c + 1) * 16 + w_q * 4];
        }

#pragma unroll
        for (int ks = 0; ks < 2; ks++) {
            uint32_t ah[2][4], al[2][4];
#pragma unroll
            for (int mt = 0; mt < 2; mt++) {
                int rb = (r0 + mt * 16 + g) * 20 + ks * 8 + q;
                ah[mt][0] = AHp[rb];
                ah[mt][1] = AHp[rb + 160];
                ah[mt][2] = AHp[rb + 4];
                ah[mt][3] = AHp[rb + 164];
                al[mt][0] = AHp[AL_OFF + rb];
                al[mt][1] = AHp[AL_OFF + rb + 160];
                al[mt][2] = AHp[AL_OFF + rb + 4];
                al[mt][3] = AHp[AL_OFF + rb + 164];
            }
#pragma unroll
            for (int nt = 0; nt < 4; nt++) {
                int nb = (n0 + nt * 8 + g) * 20 + ks * 8 + q;
                uint32_t bh0 = AHp[WH_OFF + nb], bh1 = AHp[WH_OFF + nb + 4];
                uint32_t bl0 = AHp[WL_OFF + nb], bl1 = AHp[WL_OFF + nb + 4];
#pragma unroll
                for (int mt = 0; mt < 2; mt++) {
                    mma_bf16(acc[mt][nt], ah[mt], bh0, bh1);
                    mma_bf16(acc[mt][nt], ah[mt], bl0, bl1);
                    mma_bf16(acc[mt][nt], al[mt], bh0, bh1);
                }
            }
        }

        if (more) {
            uint32_t* AH = smw + (buf ^ 1) * BUF_WORDS;
#pragma unroll
            for (int i = 0; i < 4; i++) {
                int base = a_r[i] * 20 + a_c4 * 2;
                float hx = hif(ar[i].x), hy = hif(ar[i].y), hz = hif(ar[i].z), hw = hif(ar[i].w);
                AH[base]              = bf16x2(ar[i].x, ar[i].y);
                AH[base + 1]          = bf16x2(ar[i].z, ar[i].w);
                AH[AL_OFF + base]     = bf16x2(ar[i].x - hx, ar[i].y - hy);
                AH[AL_OFF + base + 1] = bf16x2(ar[i].z - hz, ar[i].w - hw);
            }
            *(uint4*)&AH[WH_OFF + w_n * 20 + w_q * 4] = wh;
            *(uint4*)&AH[WL_OFF + w_n * 20 + w_q * 4] = wl;
        }
        __syncthreads();
    }

    // ---- epilogue ----
    if (by < 8) {
        // Q/K: split + k-pack, store [row][128 words]
        uint32_t* GH = (by < 4) ? g_QH : g_KH;
        uint32_t* GL = (by < 4) ? g_QL : g_KL;
#pragma unroll
        for (int mt = 0; mt < 2; mt++) {
            int row = row0 + r0 + mt * 16 + g;
#pragma unroll
            for (int nt = 0; nt < 4; nt++) {
                int w = ((col0 + n0 + nt * 8) >> 1) + q;
                float c0 = acc[mt][nt][0], c1 = acc[mt][nt][1];
                float c2 = acc[mt][nt][2], c3 = acc[mt][nt][3];
                float h0 = hif(c0), h1 = hif(c1), h2 = hif(c2), h3 = hif(c3);
                GH[(size_t)row * 128 + w]       = bf16x2(c0, c1);
                GL[(size_t)row * 128 + w]       = bf16x2(c0 - h0, c1 - h1);
                GH[(size_t)(row + 8) * 128 + w] = bf16x2(c2, c3);
                GL[(size_t)(row + 8) * 128 + w] = bf16x2(c2 - h2, c3 - h3);
            }
        }
    } else {
        // V: stage fp32 to smem, transpose, split + token-pair pack -> g_VH/g_VL
        __syncthreads();
        float* st = (float*)smw;             // [128][65]
#pragma unroll
        for (int mt = 0; mt < 2; mt++) {
            int r = r0 + mt * 16 + g;
#pragma unroll
            for (int nt = 0; nt < 4; nt++) {
                int cc = n0 + nt * 8 + 2 * q;
                st[r * 65 + cc]       = acc[mt][nt][0];
                st[r * 65 + cc + 1]   = acc[mt][nt][1];
                st[(r + 8) * 65 + cc]     = acc[mt][nt][2];
                st[(r + 8) * 65 + cc + 1] = acc[mt][nt][3];
            }
        }
        __syncthreads();
#pragma unroll
        for (int i = 0; i < 16; i++) {
            int idx = tid + i * 256;         // 4096: [64 cols][64 row-pairs]
            int r2 = idx & 63;
            int cc = idx >> 6;
            float v0 = st[(2 * r2) * 65 + cc];
            float v1 = st[(2 * r2 + 1) * 65 + cc];
            float h0 = hif(v0), h1 = hif(v1);
            size_t widx = (size_t)(col0 + cc) * 4096 + (row0 >> 1) + r2;
            g_VH[widx] = bf16x2(v0, v1);
            g_VL[widx] = bf16x2(v0 - h0, v1 - h1);
        }
    }
}

// ---------------------------------------------------------------------------
// Lambda scalar
// ---------------------------------------------------------------------------
__global__ void lambda_kernel(const float* __restrict__ lq1, const float* __restrict__ lk1,
                              const float* __restrict__ lq2, const float* __restrict__ lk2)
{
    __shared__ float r1[4], r2[4];
    int t = threadIdx.x;
    float d1 = lq1[t] * lk1[t];
    float d2 = lq2[t] * lk2[t];
#pragma unroll
    for (int o = 16; o; o >>= 1) {
        d1 += __shfl_xor_sync(0xffffffffu, d1, o);
        d2 += __shfl_xor_sync(0xffffffffu, d2, o);
    }
    if ((t & 31) == 0) { r1[t >> 5] = d1; r2[t >> 5] = d2; }
    __syncthreads();
    if (t == 0) {
        float a = r1[0] + r1[1] + r1[2] + r1[3];
        float b = r2[0] + r2[1] + r2[2] + r2[3];
        g_lambda = expf(a) - expf(b) + LAMBDA_INIT;
    }
}

// ===========================================================================
// Tensor-core flash attention, one stream per CTA.
// grid (16 q-tiles, 4 batch, 2 stream), 256 threads (8 warps x 16 query rows).
// k-tile = 64 keys. 3x bf16 split everywhere (incl. P).
// Smem (uint32 words): Qh[128][68] Ql[128][68] Kh[64][68] Kl[64][68]
//                      Vh[128][36] Vl[128][36]
// ===========================================================================
#define AQS 68
#define AVS 36
#define OFF_QL  (128 * AQS)
#define OFF_KH  (2 * 128 * AQS)
#define OFF_KL  (OFF_KH + 64 * AQS)
#define OFF_VH  (OFF_KL + 64 * AQS)
#define OFF_VL  (OFF_VH + 128 * AVS)
#define ATT_WORDS (OFF_VL + 128 * AVS)
#define ATT_SMEM (ATT_WORDS * 4)

__global__ __launch_bounds__(256) void attn_tc_kernel()
{
    extern __shared__ uint32_t sm[];
    uint32_t* Qh = sm;
    uint32_t* Ql = sm + OFF_QL;
    uint32_t* Kh = sm + OFF_KH;
    uint32_t* Kl = sm + OFF_KL;
    uint32_t* Vh = sm + OFF_VH;
    uint32_t* Vl = sm + OFF_VL;

    const int tid = threadIdx.x;
    const int lane = tid & 31;
    const int wid = tid >> 5;            // warp = 16 query rows
    const int g = lane >> 2;
    const int q = lane & 3;
    const int qt = blockIdx.x;
    const int b = blockIdx.y;
    const int s = blockIdx.z;
    const int qrow0 = qt * 128;

    // ---- load Q tile (hi+lo) into smem ----
    {
        const size_t qbase = ((size_t)(b * T_SEQ + qrow0)) * 128 + s * 64;
#pragma unroll
        for (int i = 0; i < 8; i++) {
            int idx = tid + i * 256;         // 2048 uint4
            int r = idx >> 4, w4 = (idx & 15) * 4;
            *(uint4*)&Qh[r * AQS + w4] = *(const uint4*)&g_QH[qbase + (size_t)r * 128 + w4];
            *(uint4*)&Ql[r * AQS + w4] = *(const uint4*)&g_QL[qbase + (size_t)r * 128 + w4];
        }
    }

    float m0 = -1e30f, m1 = -1e30f, l0 = 0.f, l1 = 0.f;
    float o[16][4];
#pragma unroll
    for (int nf = 0; nf < 16; nf++)
#pragma unroll
        for (int i = 0; i < 4; i++) o[nf][i] = 0.f;

    const int gi0 = qrow0 + wid * 16 + g;
    const int gi1 = gi0 + 8;
    const int nkt = min(2 * qt + 3, 32);

    const size_t kbase = ((size_t)(b * T_SEQ)) * 128 + s * 64;
    const size_t vbase = (size_t)b * 1024;

    for (int kt = 0; kt < nkt; kt++) {
        __syncthreads();
        // ---- load K tile [64][64w] hi+lo ----
#pragma unroll
        for (int i = 0; i < 4; i++) {
            int idx = tid + i * 256;         // 1024 uint4
            int r = idx >> 4, w4 = (idx & 15) * 4;
            size_t gsrc = kbase + (size_t)(kt * 64 + r) * 128 + w4;
            *(uint4*)&Kh[r * AQS + w4] = *(const uint4*)&g_KH[gsrc];
            *(uint4*)&Kl[r * AQS + w4] = *(const uint4*)&g_KL[gsrc];
        }
        // ---- load V^T tile [128 dims][32w] hi+lo ----
#pragma unroll
        for (int i = 0; i < 4; i++) {
            int idx = tid + i * 256;         // 1024 uint4
            int d = idx >> 3, w4 = (idx & 7) * 4;
            size_t gsrc = (size_t)d * 4096 + vbase + kt * 32 + w4;
            *(uint4*)&Vh[d * AVS + w4] = *(const uint4*)&g_VH[gsrc];
            *(uint4*)&Vl[d * AVS + w4] = *(const uint4*)&g_VL[gsrc];
        }
        __syncthreads();

        // ---- S = Q K^T (3x split) ----
        float sc[8][4];
#pragma unroll
        for (int nf = 0; nf < 8; nf++)
#pragma unroll
            for (int i = 0; i < 4; i++) sc[nf][i] = 0.f;

#pragma unroll
        for (int ks = 0; ks < 8; ks++) {
            uint32_t ah[4], al[4];
            int rb = (wid * 16 + g) * AQS + ks * 8 + q;
            ah[0] = Qh[rb];            ah[1] = Qh[rb + 8 * AQS];
            ah[2] = Qh[rb + 4];        ah[3] = Qh[rb + 8 * AQS + 4];
            al[0] = Ql[rb];            al[1] = Ql[rb + 8 * AQS];
            al[2] = Ql[rb + 4];        al[3] = Ql[rb + 8 * AQS + 4];
#pragma unroll
            for (int nf = 0; nf < 8; nf++) {
                int nb = (nf * 8 + g) * AQS + ks * 8 + q;
                uint32_t bh0 = Kh[nb], bh1 = Kh[nb + 4];
                uint32_t bl0 = Kl[nb], bl1 = Kl[nb + 4];
                mma_bf16(sc[nf], ah, bh0, bh1);
                mma_bf16(sc[nf], ah, bl0, bl1);
                mma_bf16(sc[nf], al, bh0, bh1);
            }
        }

        // ---- mask + scale ----
#pragma unroll
        for (int nf = 0; nf < 8; nf++) {
            int j0 = kt * 64 + nf * 8 + 2 * q;
            sc[nf][0] = (j0     > gi0 + 1) ? -1e30f : sc[nf][0] * SCALE_F;
            sc[nf][1] = (j0 + 1 > gi0 + 1) ? -1e30f : sc[nf][1] * SCALE_F;
            sc[nf][2] = (j0     > gi1 + 1) ? -1e30f : sc[nf][2] * SCALE_F;
            sc[nf][3] = (j0 + 1 > gi1 + 1) ? -1e30f : sc[nf][3] * SCALE_F;
        }

        // ---- online softmax (rows gi0, gi1) ----
        float mt0 = -1e30f, mt1 = -1e30f;
#pragma unroll
        for (int nf = 0; nf < 8; nf++) {
            mt0 = fmaxf(mt0, fmaxf(sc[nf][0], sc[nf][1]));
            mt1 = fmaxf(mt1, fmaxf(sc[nf][2], sc[nf][3]));
        }
        mt0 = fmaxf(mt0, __shfl_xor_sync(0xffffffffu, mt0, 1));
        mt0 = fmaxf(mt0, __shfl_xor_sync(0xffffffffu, mt0, 2));
        mt1 = fmaxf(mt1, __shfl_xor_sync(0xffffffffu, mt1, 1));
        mt1 = fmaxf(mt1, __shfl_xor_sync(0xffffffffu, mt1, 2));
        float mn0 = fmaxf(m0, mt0), mn1 = fmaxf(m1, mt1);
        float cr0 = __expf(m0 - mn0), cr1 = __expf(m1 - mn1);
        m0 = mn0; m1 = mn1;

        float ls0 = 0.f, ls1 = 0.f;
#pragma unroll
        for (int nf = 0; nf < 8; nf++) {
            sc[nf][0] = __expf(sc[nf][0] - mn0); ls0 += sc[nf][0];
            sc[nf][1] = __expf(sc[nf][1] - mn0); ls0 += sc[nf][1];
            sc[nf][2] = __expf(sc[nf][2] - mn1); ls1 += sc[nf][2];
            sc[nf][3] = __expf(sc[nf][3] - mn1); ls1 += sc[nf][3];
        }
        ls0 += __shfl_xor_sync(0xffffffffu, ls0, 1);
        ls0 += __shfl_xor_sync(0xffffffffu, ls0, 2);
        ls1 += __shfl_xor_sync(0xffffffffu, ls1, 1);
        ls1 += __shfl_xor_sync(0xffffffffu, ls1, 2);
        l0 = l0 * cr0 + ls0;
        l1 = l1 * cr1 + ls1;

#pragma unroll
        for (int nf = 0; nf < 16; nf++) {
            o[nf][0] *= cr0; o[nf][1] *= cr0;
            o[nf][2] *= cr1; o[nf][3] *= cr1;
        }

        // ---- O += P V (P split hi/lo in-register) ----
#pragma unroll
        for (int ks = 0; ks < 4; ks++) {
            const float* sA = sc[2 * ks];
            const float* sB = sc[2 * ks + 1];
            uint32_t ph[4], pl[4];
            float hA0 = hif(sA[0]), hA1 = hif(sA[1]), hA2 = hif(sA[2]), hA3 = hif(sA[3]);
            float hB0 = hif(sB[0]), hB1 = hif(sB[1]), hB2 = hif(sB[2]), hB3 = hif(sB[3]);
            ph[0] = bf16x2(sA[0], sA[1]);
            ph[1] = bf16x2(sA[2], sA[3]);
            ph[2] = bf16x2(sB[0], sB[1]);
            ph[3] = bf16x2(sB[2], sB[3]);
            pl[0] = bf16x2(sA[0] - hA0, sA[1] - hA1);
            pl[1] = bf16x2(sA[2] - hA2, sA[3] - hA3);
            pl[2] = bf16x2(sB[0] - hB0, sB[1] - hB1);
            pl[3] = bf16x2(sB[2] - hB2, sB[3] - hB3);
#pragma unroll
            for (int nf = 0; nf < 16; nf++) {
                int nb = (nf * 8 + g) * AVS + ks * 8 + q;
                uint32_t vh0 = Vh[nb], vh1 = Vh[nb + 4];
                uint32_t vl0 = Vl[nb], vl1 = Vl[nb + 4];
                mma_bf16(o[nf], ph, vh0, vh1);
                mma_bf16(o[nf], ph, vl0, vl1);
                mma_bf16(o[nf], pl, vh0, vh1);
            }
        }
    }

    // ---- epilogue: normalize, store per-stream output ----
    float* Og = s == 0 ? g_O1 : g_O2;
    float inv0 = 1.f / l0;
    float inv1 = 1.f / l1;
    float* r0p = Og + ((size_t)(b * T_SEQ) + gi0) * 128;
    float* r1p = Og + ((size_t)(b * T_SEQ) + gi1) * 128;
#pragma unroll
    for (int nf = 0; nf < 16; nf++) {
        int cc = nf * 8 + 2 * q;
        *(float2*)&r0p[cc] = make_float2(o[nf][0] * inv0, o[nf][1] * inv0);
        *(float2*)&r1p[cc] = make_float2(o[nf][2] * inv1, o[nf][3] * inv1);
    }
}

// ---------------------------------------------------------------------------
// Combine: out = O1 - lambda * O2
// ---------------------------------------------------------------------------
__global__ void combine_kernel(float* __restrict__ out)
{
    const float lbd = g_lambda;
    int idx = blockIdx.x * 256 + threadIdx.x;      // over 262144 float4
    float4 a = *(const float4*)&g_O1[idx * 4];
    float4 c = *(const float4*)&g_O2[idx * 4];
    float4 r;
    r.x = a.x - lbd * c.x;
    r.y = a.y - lbd * c.y;
    r.z = a.z - lbd * c.z;
    r.w = a.w - lbd * c.w;
    *(float4*)&out[idx * 4] = r;
}

// ---------------------------------------------------------------------------
// kernel_launch
// ---------------------------------------------------------------------------
extern "C" void kernel_launch(void* const* d_in, const int* in_sizes, int n_in,
                              void* d_out, int out_size)
{
    const float* q   = (const float*)d_in[0];
    const float* k   = (const float*)d_in[1];
    const float* v   = (const float*)d_in[2];
    const float* Wq  = (const float*)d_in[3];
    const float* Wk  = (const float*)d_in[4];
    const float* Wv  = (const float*)d_in[5];
    const float* lq1 = (const float*)d_in[6];
    const float* lk1 = (const float*)d_in[7];
    const float* lq2 = (const float*)d_in[8];
    const float* lk2 = (const float*)d_in[9];
    float* out = (float*)d_out;

    uint32_t *wqth, *wqtl, *wkth, *wktl, *wvth, *wvtl;
    cudaGetSymbolAddress((void**)&wqth, g_WqTH);
    cudaGetSymbolAddress((void**)&wqtl, g_WqTL);
    cudaGetSymbolAddress((void**)&wkth, g_WkTH);
    cudaGetSymbolAddress((void**)&wktl, g_WkTL);
    cudaGetSymbolAddress((void**)&wvth, g_WvTH);
    cudaGetSymbolAddress((void**)&wvtl, g_WvTL);

    wsplit_kernel<<<(NQK * 512) / 256, 256>>>(Wq, wqth, wqtl, NQK);
    wsplit_kernel<<<(NQK * 512) / 256, 256>>>(Wk, wkth, wktl, NQK);
    wsplit_kernel<<<(HO  * 512) / 256, 256>>>(Wv, wvth, wvtl, HO);

    cudaFuncSetAttribute(gemm_tc_kernel,
                         cudaFuncAttributeMaxDynamicSharedMemorySize, GEMM_SMEM);
    gemm_tc_kernel<<<dim3(64, 10), 256, GEMM_SMEM>>>(q, k, v);

    lambda_kernel<<<1, 128>>>(lq1, lk1, lq2, lk2);

    cudaFuncSetAttribute(attn_tc_kernel,
                         cudaFuncAttributeMaxDynamicSharedMemorySize, ATT_SMEM);
    attn_tc_kernel<<<dim3(16, B_BATCH, 2), 256, ATT_SMEM>>>();

    combine_kernel<<<1024, 256>>>(out);
}